// round 16
// baseline (speedup 1.0000x reference)
#include <cuda_runtime.h>
#include <cuda_fp16.h>
#include <cuda_bf16.h>

#define N_NODES 100000
#define IN_F 64
#define SLOTS 32
#define OV_MAX 4096

// Scratch
__device__ int g_cnt[N_NODES];                    // per-node fill count
__device__ int g_slot[(size_t)N_NODES * SLOTS];   // bucketed src ids (12.8MB)
__device__ int g_ov_cnt;
__device__ int g_ov_dst[OV_MAX];
__device__ int g_ov_src[OV_MAX];
__device__ __half g_yh[(size_t)N_NODES * 64];     // y = x @ W_lin^T, fp16 (12.8MB)

// ---------------------------------------------------------------------------
// Packed f32x2 FMA (Blackwell FFMA2 — PTX only)
// ---------------------------------------------------------------------------
__device__ __forceinline__ unsigned long long fma_f32x2(unsigned long long a,
                                                        unsigned long long b,
                                                        unsigned long long c) {
    unsigned long long d;
    asm("fma.rn.f32x2 %0, %1, %2, %3;" : "=l"(d) : "l"(a), "l"(b), "l"(c));
    return d;
}
__device__ __forceinline__ unsigned long long pack_f32x2(float lo, float hi) {
    unsigned long long r;
    asm("mov.b64 %0, {%1, %2};" : "=l"(r) : "f"(lo), "f"(hi));
    return r;
}
__device__ __forceinline__ float sum_f32x2(unsigned long long v) {
    float lo, hi;
    asm("mov.b64 {%0, %1}, %2;" : "=f"(lo), "=f"(hi) : "l"(v));
    return lo + hi;
}

// ---------------------------------------------------------------------------
// K2: single-pass bucket fill (cnt pre-zeroed by cudaMemsetAsync).
// ---------------------------------------------------------------------------
__global__ void __launch_bounds__(256)
bucket_fill_kernel(const int* __restrict__ src,
                   const int* __restrict__ dst,
                   int E4, int E) {
    const int q = blockIdx.x * 256 + threadIdx.x;
    const int4* dst4 = (const int4*)dst;
    const int4* src4 = (const int4*)src;

    if (q < E4) {
        int4 d = __ldg(dst4 + q);
        int4 s = __ldg(src4 + q);
        int p0 = atomicAdd(g_cnt + d.x, 1);
        int p1 = atomicAdd(g_cnt + d.y, 1);
        int p2 = atomicAdd(g_cnt + d.z, 1);
        int p3 = atomicAdd(g_cnt + d.w, 1);
        if (p0 < SLOTS) g_slot[(size_t)d.x * SLOTS + p0] = s.x;
        else { int o = atomicAdd(&g_ov_cnt, 1); if (o < OV_MAX) { g_ov_dst[o] = d.x; g_ov_src[o] = s.x; } }
        if (p1 < SLOTS) g_slot[(size_t)d.y * SLOTS + p1] = s.y;
        else { int o = atomicAdd(&g_ov_cnt, 1); if (o < OV_MAX) { g_ov_dst[o] = d.y; g_ov_src[o] = s.y; } }
        if (p2 < SLOTS) g_slot[(size_t)d.z * SLOTS + p2] = s.z;
        else { int o = atomicAdd(&g_ov_cnt, 1); if (o < OV_MAX) { g_ov_dst[o] = d.z; g_ov_src[o] = s.z; } }
        if (p3 < SLOTS) g_slot[(size_t)d.w * SLOTS + p3] = s.w;
        else { int o = atomicAdd(&g_ov_cnt, 1); if (o < OV_MAX) { g_ov_dst[o] = d.w; g_ov_src[o] = s.w; } }
    } else {
        // scalar tail edges
        int e = (E4 << 2) + (q - E4);
        if (e < E) {
            int d = __ldg(dst + e);
            int s = __ldg(src + e);
            int p = atomicAdd(g_cnt + d, 1);
            if (p < SLOTS) g_slot[(size_t)d * SLOTS + p] = s;
            else { int o = atomicAdd(&g_ov_cnt, 1); if (o < OV_MAX) { g_ov_dst[o] = d; g_ov_src[o] = s; } }
        }
    }
}

// ---------------------------------------------------------------------------
// K3: y = x @ W_lin^T, stored fp16. x tile staged in smem.
// ---------------------------------------------------------------------------
__global__ void __launch_bounds__(256, 3)
gemm_y_kernel(const float* __restrict__ x,
              const float* __restrict__ W_lin,
              int N, int ntiles) {
    __shared__ float sWl[64 * 64];   // [f4][o][4]
    __shared__ float sX[32 * 64];    // 8KB

    const int t = threadIdx.x;

    #pragma unroll
    for (int i = t; i < 64 * 64; i += 256) {
        int o = i >> 6;
        int f = i & 63;
        sWl[(f >> 2) * 256 + o * 4 + (f & 3)] = W_lin[i];
    }
    __syncthreads();

    int o = t & 63;
    int g = t >> 6;

    for (int tile = blockIdx.x; tile < ntiles; tile += gridDim.x) {
        int tn0 = tile * 32;
        {
            const float4* xt4 = (const float4*)(x + (size_t)tn0 * 64);
            float4* sX4 = (float4*)sX;
            int lim = (N - tn0) * 16;
            if (lim > 512) lim = 512;
            if (t < lim) sX4[t] = __ldg(xt4 + t);
            int t2 = t + 256;
            if (t2 < lim) sX4[t2] = __ldg(xt4 + t2);
        }
        __syncthreads();

        int n0 = tn0 + g * 8;
        const float* __restrict__ xbase = sX + g * 8 * 64;

        if (n0 + 7 < N) {
            unsigned long long accY[8];
            #pragma unroll
            for (int k = 0; k < 8; k++) accY[k] = 0ull;

            #pragma unroll
            for (int f4 = 0; f4 < 16; f4++) {
                ulonglong2 wl = *reinterpret_cast<const ulonglong2*>(
                                    &sWl[f4 * 256 + o * 4]);
                #pragma unroll
                for (int k = 0; k < 8; k++) {
                    ulonglong2 xv = *reinterpret_cast<const ulonglong2*>(
                                        xbase + k * 64 + f4 * 4);
                    accY[k] = fma_f32x2(xv.x, wl.x, accY[k]);
                    accY[k] = fma_f32x2(xv.y, wl.y, accY[k]);
                }
            }
            __half* yp = g_yh + (size_t)n0 * 64 + o;
            #pragma unroll
            for (int k = 0; k < 8; k++)
                yp[k * 64] = __float2half_rn(sum_f32x2(accY[k]));
        } else {
            for (int k = 0; k < 8; k++) {
                int n = n0 + k;
                if (n >= N) break;
                float ay = 0.f;
                for (int f = 0; f < 64; f++)
                    ay += xbase[k * 64 + f]
                            * sWl[(f >> 2) * 256 + o * 4 + (f & 3)];
                g_yh[(size_t)n * 64 + o] = __float2half_rn(ay);
            }
        }
        __syncthreads();
    }
}

// ---------------------------------------------------------------------------
// K4: fused gather + self-term GEMM.
// Per 32-node tile:
//   Phase A (node = t>>3, l = t&7): h[n][8l..8l+7] = sum_slots y[slot] -> sH.
//   Phase B (o = t&63, g = t>>6):  out[n][o] = sH[n][o] + x[n]·Ws[o] + b.
// Memory-bound phase A overlaps FMA-bound phase B across 4 resident blocks.
// out is written exactly ONCE (no RMW round-trip).
// ---------------------------------------------------------------------------
__global__ void __launch_bounds__(256, 4)
fused_gather_self_kernel(const float* __restrict__ x,
                         const float* __restrict__ W_self,
                         const float* __restrict__ b_lin,
                         const float* __restrict__ b_self,
                         const float* __restrict__ bias,
                         float* __restrict__ out,
                         int N, int ntiles) {
    __shared__ float sWs[64 * 64];   // [f4][o][4]  16KB
    __shared__ float sX[32 * 64];    // 8KB
    __shared__ float sH[32 * 64];    // 8KB

    const uint4* __restrict__ yh4 = (const uint4*)g_yh;
    const int t = threadIdx.x;

    #pragma unroll
    for (int i = t; i < 64 * 64; i += 256) {
        int o = i >> 6;
        int f = i & 63;
        sWs[(f >> 2) * 256 + o * 4 + (f & 3)] = W_self[i];
    }

    int o = t & 63;
    int g = t >> 6;
    float b = b_lin[o] + b_self[o] + bias[o];

    int nl = t >> 3;       // phase-A local node
    int l = t & 7;         // 16B chunk in 128B fp16 row

    __syncthreads();

    for (int tile = blockIdx.x; tile < ntiles; tile += gridDim.x) {
        int tn0 = tile * 32;

        // stage x tile (coalesced)
        {
            const float4* xt4 = (const float4*)(x + (size_t)tn0 * 64);
            float4* sX4 = (float4*)sX;
            int lim = (N - tn0) * 16;
            if (lim > 512) lim = 512;
            if (t < lim) sX4[t] = __ldg(xt4 + t);
            int t2 = t + 256;
            if (t2 < lim) sX4[t2] = __ldg(xt4 + t2);
        }

        // ---- Phase A: gather h into sH ----
        {
            int node = tn0 + nl;
            float acc[8];
            #pragma unroll
            for (int k = 0; k < 8; k++) acc[k] = 0.f;

            if (node < N) {
                int c = g_cnt[node];
                if (c > SLOTS) c = SLOTS;
                const int4* __restrict__ sp =
                    (const int4*)(g_slot + (size_t)node * SLOTS);

                int j = 0;
                int4 i4 = (c > 0) ? __ldg(sp) : make_int4(0, 0, 0, 0);
                for (; j + 4 <= c; j += 4) {
                    int4 nx = (j + 4 < c) ? __ldg(sp + (j >> 2) + 1) : i4;
                    uint4 u0 = __ldg(yh4 + (size_t)i4.x * 8 + l);
                    uint4 u1 = __ldg(yh4 + (size_t)i4.y * 8 + l);
                    uint4 u2 = __ldg(yh4 + (size_t)i4.z * 8 + l);
                    uint4 u3 = __ldg(yh4 + (size_t)i4.w * 8 + l);
                    #pragma unroll
                    for (int w = 0; w < 4; w++) {
                        unsigned int uw0 = (&u0.x)[w];
                        unsigned int uw1 = (&u1.x)[w];
                        unsigned int uw2 = (&u2.x)[w];
                        unsigned int uw3 = (&u3.x)[w];
                        float2 f0 = __half22float2(*(__half2*)&uw0);
                        float2 f1 = __half22float2(*(__half2*)&uw1);
                        float2 f2 = __half22float2(*(__half2*)&uw2);
                        float2 f3 = __half22float2(*(__half2*)&uw3);
                        acc[w * 2 + 0] += (f0.x + f1.x) + (f2.x + f3.x);
                        acc[w * 2 + 1] += (f0.y + f1.y) + (f2.y + f3.y);
                    }
                    i4 = nx;
                }
                int rem = c - j;
                #pragma unroll
                for (int rIdx = 0; rIdx < 3; rIdx++) {
                    if (rIdx < rem) {
                        int s = (&i4.x)[rIdx];
                        uint4 u = __ldg(yh4 + (size_t)s * 8 + l);
                        #pragma unroll
                        for (int w = 0; w < 4; w++) {
                            unsigned int uw = (&u.x)[w];
                            float2 f = __half22float2(*(__half2*)&uw);
                            acc[w * 2 + 0] += f.x;
                            acc[w * 2 + 1] += f.y;
                        }
                    }
                }

                // overflow entries (expected 0)
                int oc = g_ov_cnt;
                if (oc > OV_MAX) oc = OV_MAX;
                for (int k = 0; k < oc; k++) {
                    if (g_ov_dst[k] == node) {
                        int s = g_ov_src[k];
                        uint4 u = __ldg(yh4 + (size_t)s * 8 + l);
                        #pragma unroll
                        for (int w = 0; w < 4; w++) {
                            unsigned int uw = (&u.x)[w];
                            float2 f = __half22float2(*(__half2*)&uw);
                            acc[w * 2 + 0] += f.x;
                            acc[w * 2 + 1] += f.y;
                        }
                    }
                }
            }

            float4* sH4 = (float4*)(sH + nl * 64 + l * 8);
            sH4[0] = make_float4(acc[0], acc[1], acc[2], acc[3]);
            sH4[1] = make_float4(acc[4], acc[5], acc[6], acc[7]);
        }
        __syncthreads();   // sX + sH ready

        // ---- Phase B: out = sH + x@Ws^T + b ----
        {
            int n0 = tn0 + g * 8;
            const float* __restrict__ xbase = sX + g * 8 * 64;
            const float* __restrict__ hbase = sH + g * 8 * 64;

            if (n0 + 7 < N) {
                unsigned long long accS[8];
                unsigned long long binit = pack_f32x2(b, 0.f);
                #pragma unroll
                for (int k = 0; k < 8; k++) accS[k] = binit;

                #pragma unroll
                for (int f4 = 0; f4 < 16; f4++) {
                    ulonglong2 ws = *reinterpret_cast<const ulonglong2*>(
                                        &sWs[f4 * 256 + o * 4]);
                    #pragma unroll
                    for (int k = 0; k < 8; k++) {
                        ulonglong2 xv = *reinterpret_cast<const ulonglong2*>(
                                            xbase + k * 64 + f4 * 4);
                        accS[k] = fma_f32x2(xv.x, ws.x, accS[k]);
                        accS[k] = fma_f32x2(xv.y, ws.y, accS[k]);
                    }
                }
                float* op = out + (size_t)n0 * 64 + o;
                #pragma unroll
                for (int k = 0; k < 8; k++)
                    op[k * 64] = sum_f32x2(accS[k]) + hbase[k * 64 + o];
            } else {
                for (int k = 0; k < 8; k++) {
                    int n = n0 + k;
                    if (n >= N) break;
                    float as = b + hbase[k * 64 + o];
                    for (int f = 0; f < 64; f++)
                        as += xbase[k * 64 + f]
                                * sWs[(f >> 2) * 256 + o * 4 + (f & 3)];
                    out[(size_t)n * 64 + o] = as;
                }
            }
        }
        __syncthreads();   // protect sX/sH before next tile
    }
}

// ---------------------------------------------------------------------------
// Launch. Input order: x, src, dst, W_lin, b_lin, W_self, b_self, bias
// ---------------------------------------------------------------------------
extern "C" void kernel_launch(void* const* d_in, const int* in_sizes, int n_in,
                              void* d_out, int out_size) {
    const float* x      = (const float*)d_in[0];
    const int*   src    = (const int*)d_in[1];
    const int*   dst    = (const int*)d_in[2];
    const float* W_lin  = (const float*)d_in[3];
    const float* b_lin  = (const float*)d_in[4];
    const float* W_self = (const float*)d_in[5];
    const float* b_self = (const float*)d_in[6];
    const float* bias   = (const float*)d_in[7];
    float* out = (float*)d_out;

    int N = in_sizes[0] / IN_F;   // 100000
    int E = in_sizes[1];          // 1280000
    int ntiles = (N + 31) / 32;   // 3125
    int E4 = E >> 2;

    int dev = 0, sms = 148;
    cudaGetDevice(&dev);
    cudaDeviceGetAttribute(&sms, cudaDevAttrMultiProcessorCount, dev);

    // K1: zero cnt + overflow cursor (graph-capturable memsets, no alloc)
    void* cnt_ptr = nullptr;
    void* ovc_ptr = nullptr;
    cudaGetSymbolAddress(&cnt_ptr, g_cnt);
    cudaGetSymbolAddress(&ovc_ptr, g_ov_cnt);
    cudaMemsetAsync(cnt_ptr, 0, (size_t)N_NODES * sizeof(int));
    cudaMemsetAsync(ovc_ptr, 0, sizeof(int));

    // K2: single-pass bucket fill
    int total = E4 + (E - (E4 << 2));
    bucket_fill_kernel<<<(total + 255) / 256, 256>>>(src, dst, E4, E);

    // K3: y GEMM
    int g3 = sms * 3;
    if (g3 > ntiles) g3 = ntiles;
    gemm_y_kernel<<<g3, 256>>>(x, W_lin, N, ntiles);

    // K4: fused gather + self-term
    int g4 = sms * 4;
    if (g4 > ntiles) g4 = ntiles;
    fused_gather_self_kernel<<<g4, 256>>>(x, W_self, b_lin, b_self, bias,
                                          out, N, ntiles);
}

// round 17
// speedup vs baseline: 1.2326x; 1.2326x over previous
#include <cuda_runtime.h>
#include <cuda_fp16.h>
#include <cuda_bf16.h>

#define N_NODES 100000
#define IN_F 64
#define SLOTS 32
#define OV_MAX 4096

// Scratch
__device__ int g_cnt[N_NODES];                    // per-node fill count
__device__ int g_slot[(size_t)N_NODES * SLOTS];   // bucketed src ids (12.8MB)
__device__ int g_ov_cnt;
__device__ int g_ov_dst[OV_MAX];
__device__ int g_ov_src[OV_MAX];
__device__ __half g_yh[(size_t)N_NODES * 64];     // y = x @ W_lin^T, fp16 (12.8MB)

// ---------------------------------------------------------------------------
// Packed f32x2 FMA (Blackwell FFMA2 — PTX only)
// ---------------------------------------------------------------------------
__device__ __forceinline__ unsigned long long fma_f32x2(unsigned long long a,
                                                        unsigned long long b,
                                                        unsigned long long c) {
    unsigned long long d;
    asm("fma.rn.f32x2 %0, %1, %2, %3;" : "=l"(d) : "l"(a), "l"(b), "l"(c));
    return d;
}
__device__ __forceinline__ unsigned long long pack_f32x2(float lo, float hi) {
    unsigned long long r;
    asm("mov.b64 %0, {%1, %2};" : "=l"(r) : "f"(lo), "f"(hi));
    return r;
}
__device__ __forceinline__ float sum_f32x2(unsigned long long v) {
    float lo, hi;
    asm("mov.b64 {%0, %1}, %2;" : "=f"(lo), "=f"(hi) : "l"(v));
    return lo + hi;
}

// ---------------------------------------------------------------------------
// K2: single-pass bucket fill (cnt pre-zeroed by cudaMemsetAsync).
// ---------------------------------------------------------------------------
__global__ void __launch_bounds__(256)
bucket_fill_kernel(const int* __restrict__ src,
                   const int* __restrict__ dst,
                   int E4, int E) {
    const int q = blockIdx.x * 256 + threadIdx.x;
    const int4* dst4 = (const int4*)dst;
    const int4* src4 = (const int4*)src;

    if (q < E4) {
        int4 d = __ldg(dst4 + q);
        int4 s = __ldg(src4 + q);
        int p0 = atomicAdd(g_cnt + d.x, 1);
        int p1 = atomicAdd(g_cnt + d.y, 1);
        int p2 = atomicAdd(g_cnt + d.z, 1);
        int p3 = atomicAdd(g_cnt + d.w, 1);
        if (p0 < SLOTS) g_slot[(size_t)d.x * SLOTS + p0] = s.x;
        else { int o = atomicAdd(&g_ov_cnt, 1); if (o < OV_MAX) { g_ov_dst[o] = d.x; g_ov_src[o] = s.x; } }
        if (p1 < SLOTS) g_slot[(size_t)d.y * SLOTS + p1] = s.y;
        else { int o = atomicAdd(&g_ov_cnt, 1); if (o < OV_MAX) { g_ov_dst[o] = d.y; g_ov_src[o] = s.y; } }
        if (p2 < SLOTS) g_slot[(size_t)d.z * SLOTS + p2] = s.z;
        else { int o = atomicAdd(&g_ov_cnt, 1); if (o < OV_MAX) { g_ov_dst[o] = d.z; g_ov_src[o] = s.z; } }
        if (p3 < SLOTS) g_slot[(size_t)d.w * SLOTS + p3] = s.w;
        else { int o = atomicAdd(&g_ov_cnt, 1); if (o < OV_MAX) { g_ov_dst[o] = d.w; g_ov_src[o] = s.w; } }
    } else {
        int e = (E4 << 2) + (q - E4);
        if (e < E) {
            int d = __ldg(dst + e);
            int s = __ldg(src + e);
            int p = atomicAdd(g_cnt + d, 1);
            if (p < SLOTS) g_slot[(size_t)d * SLOTS + p] = s;
            else { int o = atomicAdd(&g_ov_cnt, 1); if (o < OV_MAX) { g_ov_dst[o] = d; g_ov_src[o] = s; } }
        }
    }
}

// ---------------------------------------------------------------------------
// K3: y = x @ W_lin^T (stored fp16) ; out = x @ W_self^T + b (fp32).
// x tile staged in smem (removes broadcast-LDG LSU bottleneck).
// ---------------------------------------------------------------------------
__global__ void __launch_bounds__(256, 3)
gemm_kernel(const float* __restrict__ x,
            const float* __restrict__ W_lin,
            const float* __restrict__ b_lin,
            const float* __restrict__ W_self,
            const float* __restrict__ b_self,
            const float* __restrict__ bias,
            float* __restrict__ out,
            int N, int ntiles) {
    __shared__ float sWl[64 * 64];   // [f4][o][4]
    __shared__ float sWs[64 * 64];
    __shared__ float sX[32 * 64];    // 8KB

    const int t = threadIdx.x;

    #pragma unroll
    for (int i = t; i < 64 * 64; i += 256) {
        int o = i >> 6;
        int f = i & 63;
        int dsti = (f >> 2) * 256 + o * 4 + (f & 3);
        sWl[dsti] = W_lin[i];
        sWs[dsti] = W_self[i];
    }
    __syncthreads();

    int o = t & 63;
    int g = t >> 6;
    float b = b_lin[o] + b_self[o] + bias[o];

    for (int tile = blockIdx.x; tile < ntiles; tile += gridDim.x) {
        int tn0 = tile * 32;

        // stage x tile (coalesced)
        {
            const float4* xt4 = (const float4*)(x + (size_t)tn0 * 64);
            float4* sX4 = (float4*)sX;
            int lim = (N - tn0) * 16;
            if (lim > 512) lim = 512;
            if (t < lim) sX4[t] = __ldg(xt4 + t);
            int t2 = t + 256;
            if (t2 < lim) sX4[t2] = __ldg(xt4 + t2);
        }
        __syncthreads();

        int n0 = tn0 + g * 8;
        const float* __restrict__ xbase = sX + g * 8 * 64;

        if (n0 + 7 < N) {
            unsigned long long accY[8], accS[8];
            unsigned long long binit = pack_f32x2(b, 0.f);
            #pragma unroll
            for (int k = 0; k < 8; k++) { accY[k] = 0ull; accS[k] = binit; }

            #pragma unroll
            for (int f4 = 0; f4 < 16; f4++) {
                ulonglong2 wl = *reinterpret_cast<const ulonglong2*>(
                                    &sWl[f4 * 256 + o * 4]);
                ulonglong2 ws = *reinterpret_cast<const ulonglong2*>(
                                    &sWs[f4 * 256 + o * 4]);
                #pragma unroll
                for (int k = 0; k < 8; k++) {
                    ulonglong2 xv = *reinterpret_cast<const ulonglong2*>(
                                        xbase + k * 64 + f4 * 4);
                    accY[k] = fma_f32x2(xv.x, wl.x, accY[k]);
                    accY[k] = fma_f32x2(xv.y, wl.y, accY[k]);
                    accS[k] = fma_f32x2(xv.x, ws.x, accS[k]);
                    accS[k] = fma_f32x2(xv.y, ws.y, accS[k]);
                }
            }
            __half* yp = g_yh + (size_t)n0 * 64 + o;
            float* op = out + (size_t)n0 * 64 + o;
            #pragma unroll
            for (int k = 0; k < 8; k++) {
                yp[k * 64] = __float2half_rn(sum_f32x2(accY[k]));
                op[k * 64] = sum_f32x2(accS[k]);
            }
        } else {
            for (int k = 0; k < 8; k++) {
                int n = n0 + k;
                if (n >= N) break;
                float ay = 0.f, as = b;
                for (int f = 0; f < 64; f++) {
                    float xv = xbase[k * 64 + f];
                    ay += xv * sWl[(f >> 2) * 256 + o * 4 + (f & 3)];
                    as += xv * sWs[(f >> 2) * 256 + o * 4 + (f & 3)];
                }
                g_yh[(size_t)n * 64 + o] = __float2half_rn(ay);
                out[(size_t)n * 64 + o] = as;
            }
        }
        __syncthreads();
    }
}

// ---------------------------------------------------------------------------
// K4: gather: out[n] += sum_slots y[slot[n][j]] (+ overflow), y in fp16.
// 8 threads/node; lane l loads 16B = 8 halves via ONE LDG.128 per edge-row.
// fp32 accumulation. Slot indices 4-at-a-time, prefetched a round ahead.
// ---------------------------------------------------------------------------
__global__ void __launch_bounds__(256, 4)
gather_out_kernel(float* __restrict__ out, int N) {
    const uint4* __restrict__ yh4 = (const uint4*)g_yh;   // 16B = 8 halves
    float4* __restrict__ out4 = (float4*)out;

    int idx = blockIdx.x * 256 + threadIdx.x;
    int node = idx >> 3;
    if (node >= N) return;
    int l = idx & 7;                 // 16B chunk within 128B row

    int c = g_cnt[node];
    if (c > SLOTS) c = SLOTS;
    const int4* __restrict__ sp =
        (const int4*)(g_slot + (size_t)node * SLOTS);

    float acc[8];
    #pragma unroll
    for (int k = 0; k < 8; k++) acc[k] = 0.f;

    int j = 0;
    int4 i4 = (c > 0) ? __ldg(sp) : make_int4(0, 0, 0, 0);
    for (; j + 4 <= c; j += 4) {
        int4 nx = (j + 4 < c) ? __ldg(sp + (j >> 2) + 1) : i4;
        uint4 u0 = __ldg(yh4 + (size_t)i4.x * 8 + l);
        uint4 u1 = __ldg(yh4 + (size_t)i4.y * 8 + l);
        uint4 u2 = __ldg(yh4 + (size_t)i4.z * 8 + l);
        uint4 u3 = __ldg(yh4 + (size_t)i4.w * 8 + l);

        #pragma unroll
        for (int w = 0; w < 4; w++) {
            unsigned int uw0 = (&u0.x)[w];
            unsigned int uw1 = (&u1.x)[w];
            unsigned int uw2 = (&u2.x)[w];
            unsigned int uw3 = (&u3.x)[w];
            float2 f0 = __half22float2(*(__half2*)&uw0);
            float2 f1 = __half22float2(*(__half2*)&uw1);
            float2 f2 = __half22float2(*(__half2*)&uw2);
            float2 f3 = __half22float2(*(__half2*)&uw3);
            acc[w * 2 + 0] += (f0.x + f1.x) + (f2.x + f3.x);
            acc[w * 2 + 1] += (f0.y + f1.y) + (f2.y + f3.y);
        }
        i4 = nx;
    }
    // tail (0..3 edges) using the prefetched i4
    int rem = c - j;
    #pragma unroll
    for (int rIdx = 0; rIdx < 3; rIdx++) {
        if (rIdx < rem) {
            int s = (&i4.x)[rIdx];
            uint4 u = __ldg(yh4 + (size_t)s * 8 + l);
            #pragma unroll
            for (int w = 0; w < 4; w++) {
                unsigned int uw = (&u.x)[w];
                float2 f = __half22float2(*(__half2*)&uw);
                acc[w * 2 + 0] += f.x;
                acc[w * 2 + 1] += f.y;
            }
        }
    }

    // overflow entries (expected 0)
    int oc = g_ov_cnt;
    if (oc > OV_MAX) oc = OV_MAX;
    for (int k = 0; k < oc; k++) {
        if (g_ov_dst[k] == node) {
            int s = g_ov_src[k];
            uint4 u = __ldg(yh4 + (size_t)s * 8 + l);
            #pragma unroll
            for (int w = 0; w < 4; w++) {
                unsigned int uw = (&u.x)[w];
                float2 f = __half22float2(*(__half2*)&uw);
                acc[w * 2 + 0] += f.x;
                acc[w * 2 + 1] += f.y;
            }
        }
    }

    // out row: 8 fp32 features at offset l*8 -> two float4 RMWs
    size_t obase = (size_t)node * 16 + l * 2;
    float4 c0 = out4[obase];
    float4 c1 = out4[obase + 1];
    c0.x += acc[0]; c0.y += acc[1]; c0.z += acc[2]; c0.w += acc[3];
    c1.x += acc[4]; c1.y += acc[5]; c1.z += acc[6]; c1.w += acc[7];
    out4[obase] = c0;
    out4[obase + 1] = c1;
}

// ---------------------------------------------------------------------------
// Launch. Input order: x, src, dst, W_lin, b_lin, W_self, b_self, bias
// ---------------------------------------------------------------------------
extern "C" void kernel_launch(void* const* d_in, const int* in_sizes, int n_in,
                              void* d_out, int out_size) {
    const float* x      = (const float*)d_in[0];
    const int*   src    = (const int*)d_in[1];
    const int*   dst    = (const int*)d_in[2];
    const float* W_lin  = (const float*)d_in[3];
    const float* b_lin  = (const float*)d_in[4];
    const float* W_self = (const float*)d_in[5];
    const float* b_self = (const float*)d_in[6];
    const float* bias   = (const float*)d_in[7];
    float* out = (float*)d_out;

    int N = in_sizes[0] / IN_F;   // 100000
    int E = in_sizes[1];          // 1280000
    int ntiles = (N + 31) / 32;   // 3125
    int E4 = E >> 2;

    int dev = 0, sms = 148;
    cudaGetDevice(&dev);
    cudaDeviceGetAttribute(&sms, cudaDevAttrMultiProcessorCount, dev);

    // K1: zero cnt + overflow cursor (graph-capturable memsets, no alloc)
    void* cnt_ptr = nullptr;
    void* ovc_ptr = nullptr;
    cudaGetSymbolAddress(&cnt_ptr, g_cnt);
    cudaGetSymbolAddress(&ovc_ptr, g_ov_cnt);
    cudaMemsetAsync(cnt_ptr, 0, (size_t)N_NODES * sizeof(int));
    cudaMemsetAsync(ovc_ptr, 0, sizeof(int));

    // K2: single-pass bucket fill
    int total = E4 + (E - (E4 << 2));
    bucket_fill_kernel<<<(total + 255) / 256, 256>>>(src, dst, E4, E);

    // K3: GEMM (y fp16 + self-term fp32)
    int g3 = sms * 3;
    if (g3 > ntiles) g3 = ntiles;
    gemm_kernel<<<g3, 256>>>(x, W_lin, b_lin, W_self, b_self, bias, out,
                             N, ntiles);

    // K4: gather (8 threads per node)
    long long gt = (long long)N * 8;
    gather_out_kernel<<<(int)((gt + 255) / 256), 256>>>(out, N);
}